// round 4
// baseline (speedup 1.0000x reference)
#include <cuda_runtime.h>

#define NN   50000
#define NE   800000
#define NG   64
#define DIN  128
#define HD   64
#define NH   4
#define FF   256   // HEADS*HID
#define NLAT 32

// ---- scratch (device globals; no allocation allowed) ----
__device__ float g_h[NN * HD];       // layer output features
__device__ float g_xl[NN * FF];      // source-side transform
__device__ float g_xr[NN * FF];      // target-side transform
__device__ float g_p[NE * NH];       // logits, then exp(logits - max)
__device__ int   g_nmax[NN * NH];    // ordered-int segment max
__device__ float g_nsum[NN * NH];    // segment sum of p
__device__ float g_agg[NN * HD];     // head-averaged aggregation
__device__ float g_pool[NG * HD];    // pooled per-graph features
__device__ int   g_src[NE];          // int32 edge sources
__device__ int   g_dst[NE];          // int32 edge destinations
__device__ int   g_batch[NN];        // int32 graph ids
__device__ int   g_is64;             // input index dtype flag

#define NMAX_INIT ((int)0x807FFFFF)  // f2o(-inf)

__device__ __forceinline__ int f2o(float f) {
    int i = __float_as_int(f);
    return i >= 0 ? i : (i ^ 0x7FFFFFFF);
}
__device__ __forceinline__ float o2f(int i) {
    return __int_as_float(i >= 0 ? i : (i ^ 0x7FFFFFFF));
}

// ---- detect whether edge_index buffer is int64 or int32 ----
__global__ void k_detect(const void* __restrict__ ei) {
    if (threadIdx.x == 0) {
        const unsigned long long* p = (const unsigned long long*)ei;
        int is64 = 1;
        for (int i = 0; i < 64; i++)
            if ((p[i] >> 32) != 0ull) { is64 = 0; break; }
        g_is64 = is64;
    }
}

// ---- convert indices to int32 once ----
__global__ void k_convert(const void* __restrict__ ei, const void* __restrict__ batch) {
    int i = blockIdx.x * 256 + threadIdx.x;
    int is64 = g_is64;
    if (i < NE) {
        if (is64) {
            g_src[i] = (int)((const long long*)ei)[i];
            g_dst[i] = (int)((const long long*)ei)[NE + i];
        } else {
            g_src[i] = ((const int*)ei)[i];
            g_dst[i] = ((const int*)ei)[NE + i];
        }
    }
    if (i < NN)
        g_batch[i] = is64 ? (int)((const long long*)batch)[i] : ((const int*)batch)[i];
}

// ---- per-layer scratch init ----
__global__ void k_init() {
    int i = blockIdx.x * 256 + threadIdx.x;
    if (i < NN * HD) g_agg[i] = 0.f;
    if (i < NN * NH) { g_nmax[i] = NMAX_INIT; g_nsum[i] = 0.f; }
}

// ---- xl = X @ Wl, xr = X @ Wr  (blockIdx.y selects matrix) ----
// Tile: 32 rows x 256 cols. 256 threads; each thread: 8 rows x 4 cols.
__global__ void k_gemm(const float* __restrict__ X, const float* __restrict__ Wl,
                       const float* __restrict__ Wr, int din) {
    __shared__ float hs[128 * 33];   // [k][row], padded stride 33 (conflict-free)
    const float* W   = blockIdx.y ? Wr : Wl;
    float*       out = blockIdx.y ? g_xr : g_xl;
    const float* Xp  = X ? X : g_h;

    int r0 = blockIdx.x * 32;
    int nrows = NN - r0; if (nrows > 32) nrows = 32;

    for (int idx = threadIdx.x; idx < 32 * din; idx += 256) {
        int i = idx / din, k = idx - i * din;
        hs[k * 33 + i] = (i < nrows) ? Xp[(size_t)(r0 + i) * din + k] : 0.f;
    }
    __syncthreads();

    int c4 = (threadIdx.x & 63) * 4;
    int rg = (threadIdx.x >> 6) * 8;
    float acc[8][4];
#pragma unroll
    for (int i = 0; i < 8; i++)
#pragma unroll
        for (int j = 0; j < 4; j++) acc[i][j] = 0.f;

#pragma unroll 4
    for (int k = 0; k < din; k++) {
        float4 w = *(const float4*)(W + (size_t)k * FF + c4);
#pragma unroll
        for (int i = 0; i < 8; i++) {
            float hv = hs[k * 33 + rg + i];        // warp-broadcast LDS
            acc[i][0] += hv * w.x;
            acc[i][1] += hv * w.y;
            acc[i][2] += hv * w.z;
            acc[i][3] += hv * w.w;
        }
    }
#pragma unroll
    for (int i = 0; i < 8; i++) {
        int r = rg + i;
        if (r < nrows) {
            float4 v = make_float4(acc[i][0], acc[i][1], acc[i][2], acc[i][3]);
            *(float4*)(out + (size_t)(r0 + r) * FF + c4) = v;
        }
    }
}

// ---- per-edge logits + segment max (warp per edge) ----
__global__ void k_logits(const float* __restrict__ att) {
    __shared__ float sa[FF];
    sa[threadIdx.x] = att[threadIdx.x];
    __syncthreads();

    int e = (blockIdx.x * 256 + threadIdx.x) >> 5;
    int lane = threadIdx.x & 31;
    if (e >= NE) return;
    int src = g_src[e];
    int dst = g_dst[e];
    const float* xl = g_xl + (size_t)src * FF;
    const float* xr = g_xr + (size_t)dst * FF;

    float a[4] = {0.f, 0.f, 0.f, 0.f};
#pragma unroll
    for (int i = 0; i < 8; i++) {
        int d = lane + 32 * i;                // head = i>>1, coalesced 128B lines
        float z = xl[d] + xr[d];
        z = fmaxf(z, 0.2f * z);               // leaky_relu(., 0.2)
        a[i >> 1] += z * sa[d];
    }
#pragma unroll
    for (int h = 0; h < 4; h++) {
        float v = a[h];
        v += __shfl_xor_sync(0xffffffffu, v, 16);
        v += __shfl_xor_sync(0xffffffffu, v, 8);
        v += __shfl_xor_sync(0xffffffffu, v, 4);
        v += __shfl_xor_sync(0xffffffffu, v, 2);
        v += __shfl_xor_sync(0xffffffffu, v, 1);
        a[h] = v;
    }
    if (lane == 0) {
        *(float4*)(g_p + (size_t)e * 4) = make_float4(a[0], a[1], a[2], a[3]);
        atomicMax(&g_nmax[dst * 4 + 0], f2o(a[0]));
        atomicMax(&g_nmax[dst * 4 + 1], f2o(a[1]));
        atomicMax(&g_nmax[dst * 4 + 2], f2o(a[2]));
        atomicMax(&g_nmax[dst * 4 + 3], f2o(a[3]));
    }
}

// ---- p = exp(logit - max); segment sum ----
__global__ void k_exp() {
    int idx = blockIdx.x * 256 + threadIdx.x;
    if (idx >= NE * NH) return;
    int e = idx >> 2, h = idx & 3;
    int dst = g_dst[e];
    float m = o2f(g_nmax[dst * 4 + h]);
    float p = expf(g_p[idx] - m);
    g_p[idx] = p;
    atomicAdd(&g_nsum[dst * 4 + h], p);
}

// ---- aggregation: agg[dst] += 0.25 * sum_h alpha_h * xl[src,h,:] ----
// 16 threads per edge, each owns 4 contiguous dims -> float4 vector atomics.
__global__ void k_agg() {
    int tid = blockIdx.x * 256 + threadIdx.x;
    int e = tid >> 4;
    int q = tid & 15;
    if (e >= NE) return;
    int src = g_src[e];
    int dst = g_dst[e];
    float4 pv = *(const float4*)(g_p + (size_t)e * 4);
    float4 sv = *(const float4*)(g_nsum + (size_t)dst * 4);
    float a0 = pv.x * 0.25f / (sv.x + 1e-16f);
    float a1 = pv.y * 0.25f / (sv.y + 1e-16f);
    float a2 = pv.z * 0.25f / (sv.z + 1e-16f);
    float a3 = pv.w * 0.25f / (sv.w + 1e-16f);
    const float4* xl = (const float4*)(g_xl + (size_t)src * FF);
    float4 v0 = xl[q], v1 = xl[16 + q], v2 = xl[32 + q], v3 = xl[48 + q];
    float4 acc;
    acc.x = a0 * v0.x + a1 * v1.x + a2 * v2.x + a3 * v3.x;
    acc.y = a0 * v0.y + a1 * v1.y + a2 * v2.y + a3 * v3.y;
    acc.z = a0 * v0.z + a1 * v1.z + a2 * v2.z + a3 * v3.z;
    acc.w = a0 * v0.w + a1 * v1.w + a2 * v2.w + a3 * v3.w;
    atomicAdd((float4*)(g_agg + (size_t)dst * HD + q * 4), acc);   // sm_90+ vector RED
}

// ---- h = leaky_relu(agg + b, 0.1) ----
__global__ void k_epi(const float* __restrict__ b) {
    int i = blockIdx.x * 256 + threadIdx.x;
    if (i >= NN * HD) return;
    float v = g_agg[i] + b[i & 63];
    g_h[i] = fmaxf(v, 0.1f * v);
}

__global__ void k_poolzero() {
    int i = blockIdx.x * 256 + threadIdx.x;
    if (i < NG * HD) g_pool[i] = 0.f;
}

__global__ void k_pool() {
    int tid = blockIdx.x * 256 + threadIdx.x;
    int n = tid >> 4, q = tid & 15;
    if (n >= NN) return;
    int g = g_batch[n];
    float4 v = *(const float4*)(g_h + (size_t)n * HD + q * 4);
    atomicAdd((float4*)(g_pool + (size_t)g * HD + q * 4), v);
}

// ---- batchnorm over graphs + FC (single block) ----
__global__ void k_bnfc(const float* __restrict__ gamma, const float* __restrict__ beta,
                       const float* __restrict__ fcW, const float* __restrict__ fcb,
                       float* __restrict__ out) {
    __shared__ float sp[NG * HD];
    __shared__ float smean[HD], srstd[HD], sgam[HD], sbet[HD];
    int t = threadIdx.x;
    for (int i = t; i < NG * HD; i += 256) sp[i] = g_pool[i];
    __syncthreads();
    if (t < HD) {
        float m = 0.f;
        for (int g = 0; g < NG; g++) m += sp[g * HD + t];
        m *= (1.f / NG);
        float v = 0.f;
        for (int g = 0; g < NG; g++) { float d = sp[g * HD + t] - m; v += d * d; }
        v *= (1.f / NG);
        smean[t] = m;
        srstd[t] = rsqrtf(v + 1e-5f);
        sgam[t] = gamma[t];
        sbet[t] = beta[t];
    }
    __syncthreads();
    for (int i = t; i < NG * HD; i += 256) {
        int d = i & (HD - 1);
        sp[i] = (sp[i] - smean[d]) * srstd[d] * sgam[d] + sbet[d];
    }
    __syncthreads();
    for (int o = t; o < NG * NLAT; o += 256) {
        int g = o >> 5, j = o & 31;
        float acc = fcb[j];
        for (int d = 0; d < HD; d++) acc += sp[g * HD + d] * fcW[j * HD + d];
        out[o] = acc;
    }
}

extern "C" void kernel_launch(void* const* d_in, const int* in_sizes, int n_in,
                              void* d_out, int out_size) {
    const float* x     = (const float*)d_in[0];
    const void*  ei    = d_in[1];
    const void*  batch = d_in[2];
    const float* Wl[3]  = {(const float*)d_in[3],  (const float*)d_in[7],  (const float*)d_in[11]};
    const float* Wr[3]  = {(const float*)d_in[4],  (const float*)d_in[8],  (const float*)d_in[12]};
    const float* att[3] = {(const float*)d_in[5],  (const float*)d_in[9],  (const float*)d_in[13]};
    const float* bia[3] = {(const float*)d_in[6],  (const float*)d_in[10], (const float*)d_in[14]};
    const float* gamma  = (const float*)d_in[15];
    const float* beta   = (const float*)d_in[16];
    const float* fcW    = (const float*)d_in[17];
    const float* fcb    = (const float*)d_in[18];
    float* out = (float*)d_out;

    const int TB = 256;
    int nInit = (NN * HD + TB - 1) / TB;
    int nGemm = (NN + 31) / 32;
    int nLog  = (NE * 32 + TB - 1) / TB;
    int nExp  = (NE * NH + TB - 1) / TB;
    int nAgg  = (NE * 16 + TB - 1) / TB;
    int nPool = (NN * 16 + TB - 1) / TB;
    int nPz   = (NG * HD + TB - 1) / TB;
    int nCvt  = (NE + TB - 1) / TB;

    k_detect <<<1, 32>>>(ei);
    k_convert<<<nCvt, TB>>>(ei, batch);

    for (int l = 0; l < 3; l++) {
        int din = (l == 0) ? DIN : HD;
        const float* Xp = (l == 0) ? x : nullptr;   // nullptr -> use g_h
        k_init  <<<nInit, TB>>>();
        k_gemm  <<<dim3(nGemm, 2), TB>>>(Xp, Wl[l], Wr[l], din);
        k_logits<<<nLog, TB>>>(att[l]);
        k_exp   <<<nExp, TB>>>();
        k_agg   <<<nAgg, TB>>>();
        k_epi   <<<nInit, TB>>>(bia[l]);
    }
    k_poolzero<<<nPz, TB>>>();
    k_pool    <<<nPool, TB>>>();
    k_bnfc    <<<1, 256>>>(gamma, beta, fcW, fcb, out);
}

// round 5
// speedup vs baseline: 1.2779x; 1.2779x over previous
#include <cuda_runtime.h>
#include <cuda_fp16.h>

#define NN   50000
#define NE   800000
#define NG   64
#define DIN  128
#define HD   64
#define NH   4
#define FF   256   // HEADS*HID
#define NLAT 32

// ---- scratch (device globals; no allocation allowed) ----
__device__ float g_h[NN * HD];          // layer output features
__device__ uint4 g_xlh[NN * FF / 8];    // fp16 source-side transform (16B-aligned rows)
__device__ uint4 g_xrh[NN * FF / 8];    // fp16 target-side transform
__device__ float g_p[NE * NH];          // logits, then exp(logits - max)
__device__ int   g_nmax[NN * NH];       // ordered-int segment max
__device__ float g_nsum[NN * NH];       // segment sum of p -> 0.25/denom
__device__ float g_agg[NN * HD];        // head-averaged aggregation
__device__ float g_pool[NG * HD];       // pooled per-graph features
__device__ int   g_src[NE];             // int32 edge sources
__device__ int   g_dst[NE];             // int32 edge destinations
__device__ int   g_batch[NN];           // int32 graph ids
__device__ int   g_is64;                // input index dtype flag

#define NMAX_INIT ((int)0x807FFFFF)  // f2o(-inf)

__device__ __forceinline__ int f2o(float f) {
    int i = __float_as_int(f);
    return i >= 0 ? i : (i ^ 0x7FFFFFFF);
}
__device__ __forceinline__ float o2f(int i) {
    return __int_as_float(i >= 0 ? i : (i ^ 0x7FFFFFFF));
}

// ---- detect whether edge_index buffer is int64 or int32 ----
__global__ void k_detect(const void* __restrict__ ei) {
    if (threadIdx.x == 0) {
        const unsigned long long* p = (const unsigned long long*)ei;
        int is64 = 1;
        for (int i = 0; i < 64; i++)
            if ((p[i] >> 32) != 0ull) { is64 = 0; break; }
        g_is64 = is64;
    }
}

// ---- convert indices to int32 once ----
__global__ void k_convert(const void* __restrict__ ei, const void* __restrict__ batch) {
    int i = blockIdx.x * 256 + threadIdx.x;
    int is64 = g_is64;
    if (i < NE) {
        if (is64) {
            g_src[i] = (int)((const long long*)ei)[i];
            g_dst[i] = (int)((const long long*)ei)[NE + i];
        } else {
            g_src[i] = ((const int*)ei)[i];
            g_dst[i] = ((const int*)ei)[NE + i];
        }
    }
    if (i < NN)
        g_batch[i] = is64 ? (int)((const long long*)batch)[i] : ((const int*)batch)[i];
}

// ---- per-layer scratch init ----
__global__ void k_init() {
    int i = blockIdx.x * 256 + threadIdx.x;
    if (i < NN * HD) g_agg[i] = 0.f;
    if (i < NN * NH) { g_nmax[i] = NMAX_INIT; g_nsum[i] = 0.f; }
}

// ---- xl = X @ Wl, xr = X @ Wr  (blockIdx.y selects matrix), fp16 output ----
// Tile: 32 rows x 256 cols. 256 threads; each thread: 8 rows x 4 cols.
__global__ void k_gemm(const float* __restrict__ X, const float* __restrict__ Wl,
                       const float* __restrict__ Wr, int din) {
    __shared__ float hs[128 * 33];   // [k][row], padded stride 33 (conflict-free)
    const float* W   = blockIdx.y ? Wr : Wl;
    __half*      out = (__half*)(blockIdx.y ? g_xrh : g_xlh);
    const float* Xp  = X ? X : g_h;

    int r0 = blockIdx.x * 32;
    int nrows = NN - r0; if (nrows > 32) nrows = 32;

    for (int idx = threadIdx.x; idx < 32 * din; idx += 256) {
        int i = idx / din, k = idx - i * din;
        hs[k * 33 + i] = (i < nrows) ? Xp[(size_t)(r0 + i) * din + k] : 0.f;
    }
    __syncthreads();

    int c4 = (threadIdx.x & 63) * 4;
    int rg = (threadIdx.x >> 6) * 8;
    float acc[8][4];
#pragma unroll
    for (int i = 0; i < 8; i++)
#pragma unroll
        for (int j = 0; j < 4; j++) acc[i][j] = 0.f;

#pragma unroll 4
    for (int k = 0; k < din; k++) {
        float4 w = *(const float4*)(W + (size_t)k * FF + c4);
#pragma unroll
        for (int i = 0; i < 8; i++) {
            float hv = hs[k * 33 + rg + i];        // warp-broadcast LDS
            acc[i][0] += hv * w.x;
            acc[i][1] += hv * w.y;
            acc[i][2] += hv * w.z;
            acc[i][3] += hv * w.w;
        }
    }
#pragma unroll
    for (int i = 0; i < 8; i++) {
        int r = rg + i;
        if (r < nrows) {
            __half2 lo = __floats2half2_rn(acc[i][0], acc[i][1]);
            __half2 hi = __floats2half2_rn(acc[i][2], acc[i][3]);
            uint2 v = make_uint2(*(unsigned*)&lo, *(unsigned*)&hi);
            *(uint2*)(out + (size_t)(r0 + r) * FF + c4) = v;
        }
    }
}

// ---- per-edge logits + segment max (warp per edge, fp16 gathers) ----
__global__ void k_logits(const float* __restrict__ att) {
    int e = (blockIdx.x * 256 + threadIdx.x) >> 5;
    int lane = threadIdx.x & 31;
    if (e >= NE) return;
    int src = g_src[e];
    int dst = g_dst[e];

    // whole fp16 row (512B) covered by one uint4 (8 halves) per lane
    uint4 av = __ldg(&g_xlh[(size_t)src * 32 + lane]);
    uint4 bv = __ldg(&g_xrh[(size_t)dst * 32 + lane]);
    float4 w0 = __ldg((const float4*)(att + lane * 8));
    float4 w1 = __ldg((const float4*)(att + lane * 8 + 4));

    const __half2* a2 = (const __half2*)&av;
    const __half2* b2 = (const __half2*)&bv;
    const float*   ws = (const float*)&w0;   // w0,w1 adjacent on stack
    float wreg[8] = {w0.x, w0.y, w0.z, w0.w, w1.x, w1.y, w1.z, w1.w};
    (void)ws;

    float acc = 0.f;
#pragma unroll
    for (int j = 0; j < 4; j++) {
        float2 fa = __half22float2(a2[j]);
        float2 fb = __half22float2(b2[j]);
        float z0 = fa.x + fb.x; z0 = fmaxf(z0, 0.2f * z0);
        float z1 = fa.y + fb.y; z1 = fmaxf(z1, 0.2f * z1);
        acc += z0 * wreg[2 * j] + z1 * wreg[2 * j + 1];
    }
    // reduce within each 8-lane group (one head per group: head = lane>>3)
    acc += __shfl_xor_sync(0xffffffffu, acc, 4);
    acc += __shfl_xor_sync(0xffffffffu, acc, 2);
    acc += __shfl_xor_sync(0xffffffffu, acc, 1);

    float h0 = __shfl_sync(0xffffffffu, acc, 0);
    float h1 = __shfl_sync(0xffffffffu, acc, 8);
    float h2 = __shfl_sync(0xffffffffu, acc, 16);
    float h3 = __shfl_sync(0xffffffffu, acc, 24);

    if (lane == 0) {
        *(float4*)(g_p + (size_t)e * 4) = make_float4(h0, h1, h2, h3);
        atomicMax(&g_nmax[dst * 4 + 0], f2o(h0));
        atomicMax(&g_nmax[dst * 4 + 1], f2o(h1));
        atomicMax(&g_nmax[dst * 4 + 2], f2o(h2));
        atomicMax(&g_nmax[dst * 4 + 3], f2o(h3));
    }
}

// ---- p = exp(logit - max); segment sum ----
__global__ void k_exp() {
    int idx = blockIdx.x * 256 + threadIdx.x;
    if (idx >= NE * NH) return;
    int e = idx >> 2, h = idx & 3;
    int dst = g_dst[e];
    float m = o2f(g_nmax[dst * 4 + h]);
    float p = expf(g_p[idx] - m);
    g_p[idx] = p;
    atomicAdd(&g_nsum[dst * 4 + h], p);
}

// ---- fold 0.25/denom into g_nsum once per node ----
__global__ void k_rcp() {
    int i = blockIdx.x * 256 + threadIdx.x;
    if (i < NN * NH) g_nsum[i] = 0.25f / (g_nsum[i] + 1e-16f);
}

// ---- aggregation: agg[dst] += sum_h alpha_h * xl[src,h,:] (fp16 gathers) ----
// 16 threads per edge, each owns 4 contiguous dims of the 64-dim output.
__global__ void k_agg() {
    int tid = blockIdx.x * 256 + threadIdx.x;
    int e = tid >> 4;
    int q = tid & 15;
    if (e >= NE) return;
    int src = g_src[e];
    int dst = g_dst[e];
    float4 pv = *(const float4*)(g_p + (size_t)e * 4);
    float4 sv = __ldg((const float4*)(g_nsum + (size_t)dst * 4));
    float a0 = pv.x * sv.x;
    float a1 = pv.y * sv.y;
    float a2 = pv.z * sv.z;
    float a3 = pv.w * sv.w;

    const __half* xl = (const __half*)&g_xlh[(size_t)src * 32];
    // head h contribution: halves at h*64 + q*4 .. +3  (uint2 = 4 halves)
    float4 acc = make_float4(0.f, 0.f, 0.f, 0.f);
    float ah[4] = {a0, a1, a2, a3};
#pragma unroll
    for (int h = 0; h < 4; h++) {
        uint2 raw = __ldg((const uint2*)(xl + h * 64 + q * 4));
        float2 f0 = __half22float2(*(const __half2*)&raw.x);
        float2 f1 = __half22float2(*(const __half2*)&raw.y);
        acc.x += ah[h] * f0.x;
        acc.y += ah[h] * f0.y;
        acc.z += ah[h] * f1.x;
        acc.w += ah[h] * f1.y;
    }
    atomicAdd((float4*)(g_agg + (size_t)dst * HD + q * 4), acc);
}

// ---- h = leaky_relu(agg + b, 0.1) ----
__global__ void k_epi(const float* __restrict__ b) {
    int i = blockIdx.x * 256 + threadIdx.x;
    if (i >= NN * HD) return;
    float v = g_agg[i] + b[i & 63];
    g_h[i] = fmaxf(v, 0.1f * v);
}

__global__ void k_poolzero() {
    int i = blockIdx.x * 256 + threadIdx.x;
    if (i < NG * HD) g_pool[i] = 0.f;
}

__global__ void k_pool() {
    int tid = blockIdx.x * 256 + threadIdx.x;
    int n = tid >> 4, q = tid & 15;
    if (n >= NN) return;
    int g = g_batch[n];
    float4 v = *(const float4*)(g_h + (size_t)n * HD + q * 4);
    atomicAdd((float4*)(g_pool + (size_t)g * HD + q * 4), v);
}

// ---- batchnorm over graphs + FC (single block) ----
__global__ void k_bnfc(const float* __restrict__ gamma, const float* __restrict__ beta,
                       const float* __restrict__ fcW, const float* __restrict__ fcb,
                       float* __restrict__ out) {
    __shared__ float sp[NG * HD];
    __shared__ float smean[HD], srstd[HD], sgam[HD], sbet[HD];
    int t = threadIdx.x;
    for (int i = t; i < NG * HD; i += 256) sp[i] = g_pool[i];
    __syncthreads();
    if (t < HD) {
        float m = 0.f;
        for (int g = 0; g < NG; g++) m += sp[g * HD + t];
        m *= (1.f / NG);
        float v = 0.f;
        for (int g = 0; g < NG; g++) { float d = sp[g * HD + t] - m; v += d * d; }
        v *= (1.f / NG);
        smean[t] = m;
        srstd[t] = rsqrtf(v + 1e-5f);
        sgam[t] = gamma[t];
        sbet[t] = beta[t];
    }
    __syncthreads();
    for (int i = t; i < NG * HD; i += 256) {
        int d = i & (HD - 1);
        sp[i] = (sp[i] - smean[d]) * srstd[d] * sgam[d] + sbet[d];
    }
    __syncthreads();
    for (int o = t; o < NG * NLAT; o += 256) {
        int g = o >> 5, j = o & 31;
        float acc = fcb[j];
        for (int d = 0; d < HD; d++) acc += sp[g * HD + d] * fcW[j * HD + d];
        out[o] = acc;
    }
}

extern "C" void kernel_launch(void* const* d_in, const int* in_sizes, int n_in,
                              void* d_out, int out_size) {
    const float* x     = (const float*)d_in[0];
    const void*  ei    = d_in[1];
    const void*  batch = d_in[2];
    const float* Wl[3]  = {(const float*)d_in[3],  (const float*)d_in[7],  (const float*)d_in[11]};
    const float* Wr[3]  = {(const float*)d_in[4],  (const float*)d_in[8],  (const float*)d_in[12]};
    const float* att[3] = {(const float*)d_in[5],  (const float*)d_in[9],  (const float*)d_in[13]};
    const float* bia[3] = {(const float*)d_in[6],  (const float*)d_in[10], (const float*)d_in[14]};
    const float* gamma  = (const float*)d_in[15];
    const float* beta   = (const float*)d_in[16];
    const float* fcW    = (const float*)d_in[17];
    const float* fcb    = (const float*)d_in[18];
    float* out = (float*)d_out;

    const int TB = 256;
    int nInit = (NN * HD + TB - 1) / TB;
    int nGemm = (NN + 31) / 32;
    int nLog  = (NE * 32 + TB - 1) / TB;
    int nExp  = (NE * NH + TB - 1) / TB;
    int nRcp  = (NN * NH + TB - 1) / TB;
    int nAgg  = (NE * 16 + TB - 1) / TB;
    int nPool = (NN * 16 + TB - 1) / TB;
    int nPz   = (NG * HD + TB - 1) / TB;
    int nCvt  = (NE + TB - 1) / TB;

    k_detect <<<1, 32>>>(ei);
    k_convert<<<nCvt, TB>>>(ei, batch);

    for (int l = 0; l < 3; l++) {
        int din = (l == 0) ? DIN : HD;
        const float* Xp = (l == 0) ? x : nullptr;   // nullptr -> use g_h
        k_init  <<<nInit, TB>>>();
        k_gemm  <<<dim3(nGemm, 2), TB>>>(Xp, Wl[l], Wr[l], din);
        k_logits<<<nLog, TB>>>(att[l]);
        k_exp   <<<nExp, TB>>>();
        k_rcp   <<<nRcp, TB>>>();
        k_agg   <<<nAgg, TB>>>();
        k_epi   <<<nInit, TB>>>(bia[l]);
    }
    k_poolzero<<<nPz, TB>>>();
    k_pool    <<<nPool, TB>>>();
    k_bnfc    <<<1, 256>>>(gamma, beta, fcW, fcb, out);
}